// round 3
// baseline (speedup 1.0000x reference)
#include <cuda_runtime.h>
#include <cstdint>

// ---------------- Problem constants ----------------
#define NB   16      // batch
#define NI   256     // in channels
#define NO   512     // out channels
#define WD   512     // w dim
#define XF   65      // FIR output spatial (64 + 1)
#define KTOT 2304    // NI * 9
#define NKT  144     // KTOT / 16

// ---------------- Device scratch (allowed: __device__ globals) ----------------
__device__ float g_styles[NB * NI];           // [n, i]
__device__ float g_wsq[NO * NI];              // [o, i] = sum_taps weight^2
__device__ float g_dcoefs[NB * NO];           // [n, o]
__device__ float g_Bp[KTOT * NO];             // [k = i*9 + (a*3+b)][o], tf32-rounded
__device__ float g_xs[NB * NI * XF * XF];     // FIR-filtered, style-modulated, tf32-rounded

__device__ __forceinline__ float tf32r(float x) {
    float r;
    asm("cvt.rna.tf32.f32 %0, %1;\n" : "=f"(r) : "f"(x));
    return r;
}

// ---------------- K1: styles[n,i] = (w[n,:] . affine_w[i,:]) / sqrt(512) + affine_b[i] ----------------
__global__ void k_styles(const float* __restrict__ w,
                         const float* __restrict__ aw,
                         const float* __restrict__ ab) {
    __shared__ float sw[WD];
    const int n = blockIdx.x;
    const int i = threadIdx.x;
    for (int d = threadIdx.x; d < WD; d += 256) sw[d] = w[n * WD + d];
    __syncthreads();
    const float* __restrict__ row = aw + (size_t)i * WD;
    float acc = 0.f;
#pragma unroll 8
    for (int d = 0; d < WD; d++) acc += sw[d] * row[d];
    g_styles[n * NI + i] = acc * 0.04419417382415922f + ab[i];  // 1/sqrt(512)
}

// ---------------- K2: pack weight -> Bp[k][o] (tf32), and wsq[o][i] ----------------
__global__ void k_pack(const float* __restrict__ weight) {
    const int gt = blockIdx.x * 256 + threadIdx.x;   // 131072 threads
    const int o = gt & (NO - 1);
    const int i = gt >> 9;
    const float* __restrict__ src = weight + ((size_t)o * NI + i) * 9;
    float s = 0.f;
#pragma unroll
    for (int t = 0; t < 9; t++) {
        float v = src[t];
        s += v * v;
        g_Bp[(i * 9 + t) * NO + o] = tf32r(v);
    }
    g_wsq[o * NI + i] = s;
}

// ---------------- K3: dcoefs[n,o] = rsqrt(sum_i styles^2 * wsq + 1e-8) ----------------
__global__ void k_dcoefs() {
    __shared__ float s2[NI];
    const int n = blockIdx.x;
    const int o = threadIdx.x;       // 512 threads
    if (o < NI) { float s = g_styles[n * NI + o]; s2[o] = s * s; }
    __syncthreads();
    const float* __restrict__ wr = g_wsq + (size_t)o * NI;
    float acc = 0.f;
#pragma unroll 8
    for (int i = 0; i < NI; i++) acc += s2[i] * wr[i];
    g_dcoefs[n * NO + o] = rsqrtf(acc + 1e-8f);
}

// ---------------- K4: FIR (separable [1,3,3,1]/8, pad 2) + style modulate -> g_xs (65x65, tf32) ----------------
__global__ void k_fir(const float* __restrict__ x) {
    __shared__ float sIn[64][68];    // input row, padded 2 left / 2 right
    __shared__ float sTmp[68][66];   // horizontal pass, padded 2 top / 2 bottom
    const int plane = blockIdx.x;    // n*256 + i
    const float* __restrict__ xp = x + (size_t)plane * 4096;
    const float st = g_styles[plane];
    const float f0 = 0.125f, f1 = 0.375f;
    const int tid = threadIdx.x;

    for (int idx = tid; idx < 64 * 68; idx += 256) {
        int r = idx / 68, c = idx % 68;
        int gc = c - 2;
        sIn[r][c] = (gc >= 0 && gc < 64) ? xp[r * 64 + gc] : 0.f;
    }
    for (int idx = tid; idx < 4 * 66; idx += 256) {   // zero pad rows 0,1,66,67 of sTmp
        int rr = idx / 66, c = idx % 66;
        sTmp[(rr < 2) ? rr : 64 + rr][c] = 0.f;
    }
    __syncthreads();
    for (int idx = tid; idx < 64 * 65; idx += 256) {  // horizontal: tmp[r][x] = sum_v f[v]*X[r][x+v-2]
        int r = idx / 65, xc = idx % 65;
        sTmp[r + 2][xc] = f0 * sIn[r][xc] + f1 * sIn[r][xc + 1]
                        + f1 * sIn[r][xc + 2] + f0 * sIn[r][xc + 3];
    }
    __syncthreads();
    float* __restrict__ outp = g_xs + (size_t)plane * (XF * XF);
    for (int idx = tid; idx < 65 * 65; idx += 256) {  // vertical
        int y = idx / 65, xc = idx % 65;
        float v = f0 * sTmp[y][xc] + f1 * sTmp[y + 1][xc]
                + f1 * sTmp[y + 2][xc] + f0 * sTmp[y + 3][xc];
        outp[idx] = tf32r(v * st);
    }
}

// ---------------- K5: implicit-GEMM conv (tf32 mma.sync), fused demod/bias/lrelu ----------------
// C[M=16384, N=512] = A[M, K=2304] * B[K, N]
//   A[m,(i,a,b)] = xs[n, i, 2*oh+2-a, 2*ow+2-b]   (always in-bounds, no predicates)
//   B[(i,a,b),o] = weight[o,i,a,b]   (pre-packed, tf32)
// Tile: 128x128x16, 8 warps of 64x32, m16n8k8 tf32, 2-stage cp.async.
__device__ __forceinline__ void mma_tf32(float c[4], const uint32_t a[4], const uint32_t b[2]) {
    asm volatile(
        "mma.sync.aligned.m16n8k8.row.col.f32.tf32.tf32.f32 "
        "{%0,%1,%2,%3}, {%4,%5,%6,%7}, {%8,%9}, {%0,%1,%2,%3};\n"
        : "+f"(c[0]), "+f"(c[1]), "+f"(c[2]), "+f"(c[3])
        : "r"(a[0]), "r"(a[1]), "r"(a[2]), "r"(a[3]), "r"(b[0]), "r"(b[1]));
}

__global__ __launch_bounds__(256, 2) void k_gemm(const float* __restrict__ bias,
                                                 float* __restrict__ out) {
    __shared__ __align__(16) float As[2][16][136];   // pad 8 -> conflict-free frag loads
    __shared__ __align__(16) float Bs[2][16][136];

    const int tid  = threadIdx.x;
    const int lane = tid & 31, wid = tid >> 5;
    const int wm = wid & 1, wn = wid >> 1;           // 2 x 4 warp grid
    const int bx = blockIdx.x, by = blockIdx.y;
    const int mblk = bx << 7;                        // 128 rows, all within one image
    const int obase0 = by << 7;
    const int n_img = mblk >> 10;
    const int g = lane >> 2, t4 = lane & 3;

    float acc[4][4][4];
#pragma unroll
    for (int a = 0; a < 4; a++)
#pragma unroll
        for (int b = 0; b < 4; b++)
#pragma unroll
            for (int e = 0; e < 4; e++) acc[a][b][e] = 0.f;

    auto load_tiles = [&](int kt, int s) {
        const int k0 = kt << 4;
#pragma unroll
        for (int j = 0; j < 8; j++) {                // A: 16x128, 4B gathers
            int idx = tid + (j << 8);
            int kl = idx >> 7, ml = idx & 127;
            int k = k0 + kl;
            int i = k / 9;
            int t = k - i * 9;
            int ta = t / 3;
            int tb = t - ta * 3;
            int m = mblk + ml;
            int oh = (m >> 5) & 31, ow = m & 31;
            int row = (oh << 1) + 2 - ta;
            int col = (ow << 1) + 2 - tb;
            const float* src = &g_xs[((size_t)((n_img << 8) + i) * 65 + row) * 65 + col];
            uint32_t dst = (uint32_t)__cvta_generic_to_shared(&As[s][kl][ml]);
            asm volatile("cp.async.ca.shared.global [%0], [%1], 4;\n" :: "r"(dst), "l"(src));
        }
#pragma unroll
        for (int j = 0; j < 2; j++) {                // B: 16x128, 16B vectors
            int idx = tid + (j << 8);
            int kl = idx >> 5, n4 = idx & 31;
            const float* src = &g_Bp[(size_t)(k0 + kl) * NO + obase0 + (n4 << 2)];
            uint32_t dst = (uint32_t)__cvta_generic_to_shared(&Bs[s][kl][n4 << 2]);
            asm volatile("cp.async.ca.shared.global [%0], [%1], 16;\n" :: "r"(dst), "l"(src));
        }
    };

    load_tiles(0, 0);
    asm volatile("cp.async.commit_group;\n");

    for (int kt = 0; kt < NKT; kt++) {
        const int s = kt & 1;
        if (kt + 1 < NKT) load_tiles(kt + 1, s ^ 1);
        asm volatile("cp.async.commit_group;\n");
        asm volatile("cp.async.wait_group 1;\n");
        __syncthreads();
#pragma unroll
        for (int kk = 0; kk < 16; kk += 8) {
            uint32_t af[4][4], bf[4][2];
#pragma unroll
            for (int mf = 0; mf < 4; mf++) {
                int r = (wm << 6) + (mf << 4) + g;
                af[mf][0] = __float_as_uint(As[s][kk + t4][r]);
                af[mf][1] = __float_as_uint(As[s][kk + t4][r + 8]);
                af[mf][2] = __float_as_uint(As[s][kk + 4 + t4][r]);
                af[mf][3] = __float_as_uint(As[s][kk + 4 + t4][r + 8]);
            }
#pragma unroll
            for (int nf = 0; nf < 4; nf++) {
                int c = (wn << 5) + (nf << 3) + g;
                bf[nf][0] = __float_as_uint(Bs[s][kk + t4][c]);
                bf[nf][1] = __float_as_uint(Bs[s][kk + 4 + t4][c]);
            }
#pragma unroll
            for (int mf = 0; mf < 4; mf++)
#pragma unroll
                for (int nf = 0; nf < 4; nf++)
                    mma_tf32(acc[mf][nf], af[mf], bf[nf]);
        }
        __syncthreads();
    }

    // Epilogue: y = lrelu(acc * dcoefs[n,o] + bias[o]) * sqrt(2)
    const float SQ2 = 1.4142135623730951f;
#pragma unroll
    for (int mf = 0; mf < 4; mf++) {
#pragma unroll
        for (int half = 0; half < 2; half++) {
            int m = mblk + (wm << 6) + (mf << 4) + g + (half << 3);
            int sp = m & 1023;   // oh*32 + ow
#pragma unroll
            for (int nf = 0; nf < 4; nf++) {
                int o0 = obase0 + (wn << 5) + (nf << 3) + (t4 << 1);
#pragma unroll
                for (int e = 0; e < 2; e++) {
                    int o = o0 + e;
                    float v = acc[mf][nf][half * 2 + e];
                    float d = g_dcoefs[(n_img << 9) + o];
                    float val = v * d + bias[o];
                    val = (val >= 0.f ? val : 0.2f * val) * SQ2;
                    out[(((size_t)(n_img << 9) + o) << 10) + sp] = val;
                }
            }
        }
    }
}

// ---------------- Launch ----------------
extern "C" void kernel_launch(void* const* d_in, const int* in_sizes, int n_in,
                              void* d_out, int out_size) {
    const float* x      = (const float*)d_in[0];  // [16,256,64,64]
    const float* w      = (const float*)d_in[1];  // [16,512]
    const float* aw     = (const float*)d_in[2];  // [256,512]
    const float* ab     = (const float*)d_in[3];  // [256]
    const float* weight = (const float*)d_in[4];  // [512,256,3,3]
    const float* bias   = (const float*)d_in[5];  // [512]
    float* out = (float*)d_out;                   // [16,512,32,32]

    k_styles<<<16, 256>>>(w, aw, ab);
    k_pack<<<512, 256>>>(weight);
    k_dcoefs<<<16, 512>>>();
    k_fir<<<NB * NI, 256>>>(x);
    k_gemm<<<dim3(128, 4), 256>>>(bias, out);
}

// round 5
// speedup vs baseline: 1.5353x; 1.5353x over previous
#include <cuda_runtime.h>
#include <cuda_fp16.h>
#include <cstdint>

// ---------------- Problem constants ----------------
#define NB   16
#define NI   256
#define NO   512
#define WD   512
#define PXY  4225      // 65*65
#define NSTG 72        // 9 taps * 8 chunks of 32 channels

// ---------------- Device scratch ----------------
__device__ float  g_styles[NB * NI];
__device__ float  g_wsq[NO * NI];
__device__ float  g_dcoefs[NB * NO];
__device__ __half g_Bh[NO * 9 * NI];             // [o][tap*256 + i]
__device__ __half g_xh[NB * NI * PXY];           // FIR out, NCHW fp16
__device__ __half g_xth[(size_t)NB * PXY * NI];  // NHWC: [n][y*65+x][i]

__device__ __forceinline__ uint32_t smem_u32(const void* p) {
    return (uint32_t)__cvta_generic_to_shared(p);
}
__device__ __forceinline__ void cp16(uint32_t dst, const void* src) {
    asm volatile("cp.async.cg.shared.global [%0], [%1], 16;\n" :: "r"(dst), "l"(src));
}

// ---------------- K1: styles ----------------
__global__ void k_styles(const float* __restrict__ w,
                         const float* __restrict__ aw,
                         const float* __restrict__ ab) {
    __shared__ float sw[WD];
    const int n = blockIdx.x;
    const int i = threadIdx.x;
    for (int d = threadIdx.x; d < WD; d += 256) sw[d] = w[n * WD + d];
    __syncthreads();
    const float* __restrict__ row = aw + (size_t)i * WD;
    float acc = 0.f;
#pragma unroll 8
    for (int d = 0; d < WD; d++) acc += sw[d] * row[d];
    g_styles[n * NI + i] = acc * 0.04419417382415922f + ab[i];
}

// ---------------- K2: pack weight -> Bh[o][t*256+i] (fp16) + wsq ----------------
__global__ void k_pack(const float* __restrict__ weight) {
    const int gt = blockIdx.x * 256 + threadIdx.x;   // 131072
    const int i = gt & (NI - 1);
    const int o = gt >> 8;
    const float* __restrict__ src = weight + ((size_t)o * NI + i) * 9;
    float s = 0.f;
#pragma unroll
    for (int t = 0; t < 9; t++) {
        float v = src[t];
        s += v * v;
        g_Bh[(size_t)o * (9 * NI) + t * NI + i] = __float2half(v);
    }
    g_wsq[o * NI + i] = s;
}

// ---------------- K3: dcoefs ----------------
__global__ void k_dcoefs() {
    __shared__ float s2[NI];
    const int n = blockIdx.x;
    const int o = threadIdx.x;  // 512
    if (o < NI) { float s = g_styles[n * NI + o]; s2[o] = s * s; }
    __syncthreads();
    const float* __restrict__ wr = g_wsq + (size_t)o * NI;
    float acc = 0.f;
#pragma unroll 8
    for (int i = 0; i < NI; i++) acc += s2[i] * wr[i];
    g_dcoefs[n * NO + o] = rsqrtf(acc + 1e-8f);
}

// ---------------- K4: FIR + modulate -> g_xh (NCHW, 65x65, fp16) ----------------
__global__ void k_fir(const float* __restrict__ x) {
    __shared__ float sIn[64][68];
    __shared__ float sTmp[68][66];
    const int plane = blockIdx.x;
    const float* __restrict__ xp = x + (size_t)plane * 4096;
    const float st = g_styles[plane];
    const float f0 = 0.125f, f1 = 0.375f;
    const int tid = threadIdx.x;

    for (int idx = tid; idx < 64 * 68; idx += 256) {
        int r = idx / 68, c = idx % 68;
        int gc = c - 2;
        sIn[r][c] = (gc >= 0 && gc < 64) ? xp[r * 64 + gc] : 0.f;
    }
    for (int idx = tid; idx < 4 * 66; idx += 256) {
        int rr = idx / 66, c = idx % 66;
        sTmp[(rr < 2) ? rr : 64 + rr][c] = 0.f;
    }
    __syncthreads();
    for (int idx = tid; idx < 64 * 65; idx += 256) {
        int r = idx / 65, xc = idx % 65;
        sTmp[r + 2][xc] = f0 * sIn[r][xc] + f1 * sIn[r][xc + 1]
                        + f1 * sIn[r][xc + 2] + f0 * sIn[r][xc + 3];
    }
    __syncthreads();
    __half* __restrict__ outp = g_xh + (size_t)plane * PXY;
    for (int idx = tid; idx < PXY; idx += 256) {
        int y = idx / 65, xc = idx % 65;
        float v = f0 * sTmp[y][xc] + f1 * sTmp[y + 1][xc]
                + f1 * sTmp[y + 2][xc] + f0 * sTmp[y + 3][xc];
        outp[idx] = __float2half(v * st);
    }
}

// ---------------- K5: NCHW -> NHWC transpose (fp16) ----------------
__global__ void k_tr() {
    __shared__ __half tile[32][34];
    const int p0 = blockIdx.x * 32;
    const int i0 = blockIdx.y * 32;
    const int n  = blockIdx.z;
    const int tx = threadIdx.x, ty = threadIdx.y;   // block (32, 8)
    const __half* __restrict__ src = g_xh + (size_t)n * NI * PXY;
#pragma unroll
    for (int j = 0; j < 4; j++) {
        int i = i0 + ty + j * 8;
        int p = p0 + tx;
        tile[ty + j * 8][tx] = (p < PXY) ? src[(size_t)i * PXY + p] : __float2half(0.f);
    }
    __syncthreads();
    __half* __restrict__ dst = g_xth + (size_t)n * PXY * NI;
#pragma unroll
    for (int j = 0; j < 4; j++) {
        int p = p0 + ty + j * 8;
        if (p < PXY) dst[(size_t)p * NI + i0 + tx] = tile[tx][ty + j * 8];
    }
}

// ---------------- K6: fp16 implicit-GEMM conv (mma.m16n8k16), fused demod/bias/lrelu ----------------
// C[M=16384, N=512] = A[M, K=2304] * B[K, N], fp16 operands, fp32 accum.
// A[m,(t,i)] = xth[n][2oh+2-ta][2ow+2-tb][i];  B in g_Bh [o][t*256+i] (k-contiguous).
// Tile 128x128x32, 8 warps of 64x32, 2-stage cp.async.
__device__ __forceinline__ void mma_f16(float c[4], const uint32_t a[4], const uint32_t b[2]) {
    asm volatile(
        "mma.sync.aligned.m16n8k16.row.col.f32.f16.f16.f32 "
        "{%0,%1,%2,%3}, {%4,%5,%6,%7}, {%8,%9}, {%0,%1,%2,%3};\n"
        : "+f"(c[0]), "+f"(c[1]), "+f"(c[2]), "+f"(c[3])
        : "r"(a[0]), "r"(a[1]), "r"(a[2]), "r"(a[3]), "r"(b[0]), "r"(b[1]));
}

__global__ __launch_bounds__(256, 2) void k_gemm(const float* __restrict__ bias,
                                                 float* __restrict__ out) {
    __shared__ __align__(16) __half As[2][128][40];   // pad 8 halfs -> conflict-free
    __shared__ __align__(16) __half Bs[2][128][40];

    const int tid  = threadIdx.x;
    const int lane = tid & 31, wid = tid >> 5;
    const int wm = wid & 1, wn = wid >> 1;            // 2 x 4 warp grid
    const int mblk = blockIdx.x << 7;                 // within one image
    const int obase = blockIdx.y << 7;
    const int n_img = mblk >> 10;
    const int g = lane >> 2, t4 = lane & 3;

    // Load mapping: thread t loads row lr = t>>1, 32B at half-offset hq=(t&1)*16.
    const int lr = tid >> 1;
    const int hq = (tid & 1) << 4;
    const int m  = mblk + lr;
    const int oh = (m >> 5) & 31, ow = m & 31;
    const __half* __restrict__ xn = g_xth + (size_t)n_img * PXY * NI;
    const __half* __restrict__ bw = g_Bh + (size_t)(obase + lr) * (9 * NI) + hq;

    float acc[4][4][4];
#pragma unroll
    for (int a = 0; a < 4; a++)
#pragma unroll
        for (int b = 0; b < 4; b++)
#pragma unroll
            for (int e = 0; e < 4; e++) acc[a][b][e] = 0.f;

    auto load_stage = [&](int s, int b) {
        const int t = s >> 3, c = s & 7;
        const int ta = t / 3, tb = t - ta * 3;
        const int y  = (oh << 1) + 2 - ta;
        const int xx = (ow << 1) + 2 - tb;
        const __half* asrc = xn + (((size_t)(y * 65 + xx)) << 8) + (c << 5) + hq;
        uint32_t ad = smem_u32(&As[b][lr][hq]);
        cp16(ad, asrc);
        cp16(ad + 16, asrc + 8);
        const __half* bsrc = bw + (t << 8) + (c << 5);
        uint32_t bd = smem_u32(&Bs[b][lr][hq]);
        cp16(bd, bsrc);
        cp16(bd + 16, bsrc + 8);
    };

    load_stage(0, 0);
    asm volatile("cp.async.commit_group;\n" ::: "memory");

    for (int s = 0; s < NSTG; s++) {
        const int b = s & 1;
        if (s + 1 < NSTG) load_stage(s + 1, b ^ 1);
        asm volatile("cp.async.commit_group;\n" ::: "memory");
        asm volatile("cp.async.wait_group 1;\n" ::: "memory");
        __syncthreads();
#pragma unroll
        for (int kk = 0; kk < 32; kk += 16) {
            uint32_t af[4][4], bf[4][2];
#pragma unroll
            for (int mf = 0; mf < 4; mf++) {
                int r = (wm << 6) + (mf << 4) + g;
                int kc = kk + (t4 << 1);
                af[mf][0] = *(const uint32_t*)&As[b][r][kc];
                af[mf][1] = *(const uint32_t*)&As[b][r + 8][kc];
                af[mf][2] = *(const uint32_t*)&As[b][r][kc + 8];
                af[mf][3] = *(const uint32_t*)&As[b][r + 8][kc + 8];
            }
#pragma unroll
            for (int nf = 0; nf < 4; nf++) {
                int c = (wn << 5) + (nf << 3) + g;
                int kc = kk + (t4 << 1);
                bf[nf][0] = *(const uint32_t*)&Bs[b][c][kc];
                bf[nf][1] = *(const uint32_t*)&Bs[b][c][kc + 8];
            }
#pragma unroll
            for (int mf = 0; mf < 4; mf++)
#pragma unroll
                for (int nf = 0; nf < 4; nf++)
                    mma_f16(acc[mf][nf], af[mf], bf[nf]);
        }
        __syncthreads();
    }

    // Epilogue: y = lrelu(acc * dcoefs[n,o] + bias[o]) * sqrt(2)
    const float SQ2 = 1.4142135623730951f;
#pragma unroll
    for (int mf = 0; mf < 4; mf++) {
#pragma unroll
        for (int half = 0; half < 2; half++) {
            int mm = mblk + (wm << 6) + (mf << 4) + g + (half << 3);
            int sp = mm & 1023;   // oh*32 + ow
#pragma unroll
            for (int nf = 0; nf < 4; nf++) {
                int o0 = obase + (wn << 5) + (nf << 3) + (t4 << 1);
#pragma unroll
                for (int e = 0; e < 2; e++) {
                    int o = o0 + e;
                    float v = acc[mf][nf][half * 2 + e];
                    float d = g_dcoefs[(n_img << 9) + o];
                    float val = v * d + bias[o];
                    val = (val >= 0.f ? val : 0.2f * val) * SQ2;
                    out[(((size_t)(n_img << 9) + o) << 10) + sp] = val;
                }
            }
        }
    }
}

// ---------------- Launch ----------------
extern "C" void kernel_launch(void* const* d_in, const int* in_sizes, int n_in,
                              void* d_out, int out_size) {
    const float* x      = (const float*)d_in[0];  // [16,256,64,64]
    const float* w      = (const float*)d_in[1];  // [16,512]
    const float* aw     = (const float*)d_in[2];  // [256,512]
    const float* ab     = (const float*)d_in[3];  // [256]
    const float* weight = (const float*)d_in[4];  // [512,256,3,3]
    const float* bias   = (const float*)d_in[5];  // [512]
    float* out = (float*)d_out;                   // [16,512,32,32]

    k_styles<<<16, 256>>>(w, aw, ab);
    k_pack<<<512, 256>>>(weight);
    k_dcoefs<<<16, 512>>>();
    k_fir<<<NB * NI, 256>>>(x);
    k_tr<<<dim3(133, 8, 16), dim3(32, 8)>>>();
    k_gemm<<<dim3(128, 4), 256>>>(bias, out);
}

// round 6
// speedup vs baseline: 1.7078x; 1.1123x over previous
#include <cuda_runtime.h>
#include <cuda_fp16.h>
#include <cstdint>

// ---------------- Problem constants ----------------
#define NB   16
#define NI   256
#define NO   512
#define WD   512
#define PXY  4225      // 65*65
#define NSTG 72        // 9 taps * 8 chunks of 32 channels

// ---------------- Device scratch ----------------
__device__ float  g_styles[NB * NI];
__device__ float  g_wsq[NO * NI];
__device__ float  g_dcoefs[NB * NO];
__device__ __half g_Bh[NO * 9 * NI];             // [o][tap*256 + i]
__device__ __half g_xth[(size_t)NB * PXY * NI];  // NHWC: [n][y*65+x][i]

__device__ __forceinline__ uint32_t smem_u32(const void* p) {
    return (uint32_t)__cvta_generic_to_shared(p);
}
__device__ __forceinline__ void cp16(uint32_t dst, const void* src) {
    asm volatile("cp.async.cg.shared.global [%0], [%1], 16;\n" :: "r"(dst), "l"(src));
}

// ---------------- K1: styles ----------------
__global__ void k_styles(const float* __restrict__ w,
                         const float* __restrict__ aw,
                         const float* __restrict__ ab) {
    __shared__ float sw[WD];
    const int n = blockIdx.x;
    const int i = threadIdx.x;
    for (int d = threadIdx.x; d < WD; d += 256) sw[d] = w[n * WD + d];
    __syncthreads();
    const float* __restrict__ row = aw + (size_t)i * WD;
    float acc = 0.f;
#pragma unroll 8
    for (int d = 0; d < WD; d++) acc += sw[d] * row[d];
    g_styles[n * NI + i] = acc * 0.04419417382415922f + ab[i];
}

// ---------------- K2: pack weight -> Bh[o][t*256+i] (fp16) + wsq ----------------
__global__ void k_pack(const float* __restrict__ weight) {
    const int gt = blockIdx.x * 256 + threadIdx.x;   // 131072
    const int i = gt & (NI - 1);
    const int o = gt >> 8;
    const float* __restrict__ src = weight + ((size_t)o * NI + i) * 9;
    float s = 0.f;
#pragma unroll
    for (int t = 0; t < 9; t++) {
        float v = src[t];
        s += v * v;
        g_Bh[(size_t)o * (9 * NI) + t * NI + i] = __float2half(v);
    }
    g_wsq[o * NI + i] = s;
}

// ---------------- K3: dcoefs ----------------
__global__ void k_dcoefs() {
    __shared__ float s2[NI];
    const int n = blockIdx.x;
    const int o = threadIdx.x;  // 512
    if (o < NI) { float s = g_styles[n * NI + o]; s2[o] = s * s; }
    __syncthreads();
    const float* __restrict__ wr = g_wsq + (size_t)o * NI;
    float acc = 0.f;
#pragma unroll 8
    for (int i = 0; i < NI; i++) acc += s2[i] * wr[i];
    g_dcoefs[n * NO + o] = rsqrtf(acc + 1e-8f);
}

// ---------------- K4: fused FIR + modulate + NHWC transpose ----------------
// Block = (strip, igroup, n): 16 channels x 13 output rows. Input rows y0-2..y0+13
// cached in smem [r][ch][69] (cols 0,1 = left pad, 2..65 = x 0..63, 66,67 = right pad,
// 68 = bank pad). Horizontal 4-tap recomputed in registers during vertical pass.
#define FW 69
#define SROW (16 * FW)     // 1104 floats per input row (16 channels)
__global__ __launch_bounds__(256) void k_fir2(const float* __restrict__ x) {
    extern __shared__ float sf[];    // 16*16*69 floats = 70656 B
    const int tid = threadIdx.x;
    const int y0 = blockIdx.x * 13;
    const int i0 = blockIdx.y << 4;
    const int n  = blockIdx.z;
    const float f0 = 0.125f, f1 = 0.375f;

    // zero pad columns (0,1,66,67) for all 16 rows x 16 channels: 1024 elems
    {
        int idx = tid;                       // 256 threads, 4 iters
#pragma unroll
        for (int it = 0; it < 4; it++, idx += 256) {
            int c4 = idx & 3;
            int ch = (idx >> 2) & 15;
            int r  = idx >> 6;
            int c  = (c4 < 2) ? c4 : 64 + c4;
            sf[r * SROW + ch * FW + c] = 0.f;
        }
    }
    // zero rows with out-of-range source (at most 2 per block)
#pragma unroll
    for (int r = 0; r < 16; r++) {
        int g = y0 - 2 + r;
        if (g < 0 || g > 63) {
            for (int idx = tid; idx < 16 * FW; idx += 256)
                sf[r * SROW + idx] = 0.f;
        }
    }
    // load valid rows: float4 per thread-iter
    {
        const float* __restrict__ xb = x + (((size_t)(n << 8) + i0) << 12);
#pragma unroll
        for (int it = 0; it < 16; it++) {
            int idx = it * 256 + tid;
            int q  = idx & 15;
            int ch = (idx >> 4) & 15;
            int r  = idx >> 8;
            int g  = y0 - 2 + r;
            if (g >= 0 && g <= 63) {
                const float4 v = *(const float4*)(xb + ((size_t)ch << 12) + (g << 6) + (q << 2));
                float* d = &sf[r * SROW + ch * FW + 2 + (q << 2)];
                d[0] = v.x; d[1] = v.y; d[2] = v.z; d[3] = v.w;
            }
        }
    }
    __syncthreads();

    // vertical pass + modulate + NHWC write
    const int ch = tid & 15;
    const int q  = tid >> 4;
    const float st = g_styles[(n << 8) + i0 + ch];
    __half* __restrict__ outp = g_xth + ((size_t)n * PXY << 8) + i0 + ch;
#pragma unroll
    for (int j = 0; j < 5; j++) {
        const int xc = q + (j << 4);
        if (xc > 64) break;
        float h[16];
#pragma unroll
        for (int r = 0; r < 16; r++) {
            const float* s = &sf[r * SROW + ch * FW + xc];
            h[r] = f0 * (s[0] + s[3]) + f1 * (s[1] + s[2]);
        }
#pragma unroll
        for (int y = 0; y < 13; y++) {
            float v = f0 * (h[y] + h[y + 3]) + f1 * (h[y + 1] + h[y + 2]);
            outp[(size_t)(((y0 + y) * 65 + xc)) << 8] = __float2half(v * st);
        }
    }
}

// ---------------- K5: fp16 implicit-GEMM conv (mma.m16n8k16), fused demod/bias/lrelu ----------------
__device__ __forceinline__ void mma_f16(float c[4], const uint32_t a[4], const uint32_t b[2]) {
    asm volatile(
        "mma.sync.aligned.m16n8k16.row.col.f32.f16.f16.f32 "
        "{%0,%1,%2,%3}, {%4,%5,%6,%7}, {%8,%9}, {%0,%1,%2,%3};\n"
        : "+f"(c[0]), "+f"(c[1]), "+f"(c[2]), "+f"(c[3])
        : "r"(a[0]), "r"(a[1]), "r"(a[2]), "r"(a[3]), "r"(b[0]), "r"(b[1]));
}

__global__ __launch_bounds__(256, 2) void k_gemm(const float* __restrict__ bias,
                                                 float* __restrict__ out) {
    __shared__ __align__(16) __half As[2][128][40];
    __shared__ __align__(16) __half Bs[2][128][40];

    const int tid  = threadIdx.x;
    const int lane = tid & 31, wid = tid >> 5;
    const int wm = wid & 1, wn = wid >> 1;
    const int mblk = blockIdx.x << 7;
    const int obase = blockIdx.y << 7;
    const int n_img = mblk >> 10;
    const int g = lane >> 2, t4 = lane & 3;

    const int lr = tid >> 1;
    const int hq = (tid & 1) << 4;
    const int m  = mblk + lr;
    const int oh = (m >> 5) & 31, ow = m & 31;
    const __half* __restrict__ xn = g_xth + (size_t)n_img * PXY * NI;
    const __half* __restrict__ bw = g_Bh + (size_t)(obase + lr) * (9 * NI) + hq;

    float acc[4][4][4];
#pragma unroll
    for (int a = 0; a < 4; a++)
#pragma unroll
        for (int b = 0; b < 4; b++)
#pragma unroll
            for (int e = 0; e < 4; e++) acc[a][b][e] = 0.f;

    auto load_stage = [&](int s, int b) {
        const int t = s >> 3, c = s & 7;
        const int ta = t / 3, tb = t - ta * 3;
        const int y  = (oh << 1) + 2 - ta;
        const int xx = (ow << 1) + 2 - tb;
        const __half* asrc = xn + (((size_t)(y * 65 + xx)) << 8) + (c << 5) + hq;
        uint32_t ad = smem_u32(&As[b][lr][hq]);
        cp16(ad, asrc);
        cp16(ad + 16, asrc + 8);
        const __half* bsrc = bw + (t << 8) + (c << 5);
        uint32_t bd = smem_u32(&Bs[b][lr][hq]);
        cp16(bd, bsrc);
        cp16(bd + 16, bsrc + 8);
    };

    load_stage(0, 0);
    asm volatile("cp.async.commit_group;\n" ::: "memory");

    for (int s = 0; s < NSTG; s++) {
        const int b = s & 1;
        if (s + 1 < NSTG) load_stage(s + 1, b ^ 1);
        asm volatile("cp.async.commit_group;\n" ::: "memory");
        asm volatile("cp.async.wait_group 1;\n" ::: "memory");
        __syncthreads();
#pragma unroll
        for (int kk = 0; kk < 32; kk += 16) {
            uint32_t af[4][4], bf[4][2];
#pragma unroll
            for (int mf = 0; mf < 4; mf++) {
                int r = (wm << 6) + (mf << 4) + g;
                int kc = kk + (t4 << 1);
                af[mf][0] = *(const uint32_t*)&As[b][r][kc];
                af[mf][1] = *(const uint32_t*)&As[b][r + 8][kc];
                af[mf][2] = *(const uint32_t*)&As[b][r][kc + 8];
                af[mf][3] = *(const uint32_t*)&As[b][r + 8][kc + 8];
            }
#pragma unroll
            for (int nf = 0; nf < 4; nf++) {
                int c = (wn << 5) + (nf << 3) + g;
                int kc = kk + (t4 << 1);
                bf[nf][0] = *(const uint32_t*)&Bs[b][c][kc];
                bf[nf][1] = *(const uint32_t*)&Bs[b][c][kc + 8];
            }
#pragma unroll
            for (int mf = 0; mf < 4; mf++)
#pragma unroll
                for (int nf = 0; nf < 4; nf++)
                    mma_f16(acc[mf][nf], af[mf], bf[nf]);
        }
        __syncthreads();
    }

    const float SQ2 = 1.4142135623730951f;
#pragma unroll
    for (int mf = 0; mf < 4; mf++) {
#pragma unroll
        for (int half = 0; half < 2; half++) {
            int mm = mblk + (wm << 6) + (mf << 4) + g + (half << 3);
            int sp = mm & 1023;
#pragma unroll
            for (int nf = 0; nf < 4; nf++) {
                int o0 = obase + (wn << 5) + (nf << 3) + (t4 << 1);
#pragma unroll
                for (int e = 0; e < 2; e++) {
                    int o = o0 + e;
                    float v = acc[mf][nf][half * 2 + e];
                    float d = g_dcoefs[(n_img << 9) + o];
                    float val = v * d + bias[o];
                    val = (val >= 0.f ? val : 0.2f * val) * SQ2;
                    out[(((size_t)(n_img << 9) + o) << 10) + sp] = val;
                }
            }
        }
    }
}

// ---------------- Launch ----------------
extern "C" void kernel_launch(void* const* d_in, const int* in_sizes, int n_in,
                              void* d_out, int out_size) {
    const float* x      = (const float*)d_in[0];  // [16,256,64,64]
    const float* w      = (const float*)d_in[1];  // [16,512]
    const float* aw     = (const float*)d_in[2];  // [256,512]
    const float* ab     = (const float*)d_in[3];  // [256]
    const float* weight = (const float*)d_in[4];  // [512,256,3,3]
    const float* bias   = (const float*)d_in[5];  // [512]
    float* out = (float*)d_out;                   // [16,512,32,32]

    cudaFuncSetAttribute(k_fir2, cudaFuncAttributeMaxDynamicSharedMemorySize, 70656);

    k_styles<<<16, 256>>>(w, aw, ab);
    k_pack<<<512, 256>>>(weight);
    k_dcoefs<<<16, 512>>>();
    k_fir2<<<dim3(5, 16, 16), 256, 70656>>>(x);
    k_gemm<<<dim3(128, 4), 256>>>(bias, out);
}